// round 6
// baseline (speedup 1.0000x reference)
#include <cuda_runtime.h>
#include <math.h>

// Problem constants
#define NN   50000
#define EE   800000
#define DD   128
#define HH   4
#define EDD  32
#define KDIM 129          // D+1 input dim
#define PST  132          // per-(n,h) stride for p: [p 0..128, c at 129, qt at 130, pad]
#define EPSF 1e-8f
#define SCALE_INV 0.08838834764831845f   // 1/sqrt(128)
#define CHALF     5.656854249492381f     // sqrt(128)/2

#define NPAD 50176        // NN padded to 256 multiple
#define NBLK 196          // NPAD/256
#define NBLK2 392         // 2*NPAD/256

// ---------------- scratch (static device globals; no allocation) -------------
__device__ float g_qs[NN * HH * DD];      // 102.4 MB raw q space
__device__ float g_p[NN * HH * PST];      // 105.6 MB  p / c / qt
__device__ float g_kt[NN * HH];           // k time components
__device__ float g_tan[NN * HH * DD];     // 102.4 MB
__device__ float g_logits[EE * HH];       // 12.8 MB (then exp values), by ORIGINAL eid
__device__ float g_m[NN * HH];
__device__ float g_den[NN * HH];
__device__ float g_agg[NN * DD];          // 25.6 MB head-fused accumulator
__device__ int   g_cnt[2 * NPAD];         // [0:NPAD) src hist, [NPAD:) dst hist
__device__ int   g_scan[2 * NPAD];
__device__ int   g_bsum[512];
__device__ int   g_offs[NN + 1];          // CSR by src
__device__ int   g_offd[NN + 1];          // CSR by dst
__device__ int   g_pos[2 * NN];
__device__ int   gs_src[EE], gs_dst[EE], gs_eid[EE];   // src-sorted
__device__ int   gd_src[EE], gd_dst[EE], gd_eid[EE];   // dst-sorted

// ---------------------------------------------------------------------------
__global__ void k_init() {
    int i = blockIdx.x * blockDim.x + threadIdx.x;
    int stride = gridDim.x * blockDim.x;
    for (int j = i; j < NN * DD; j += stride) g_agg[j] = 0.f;
    for (int j = i; j < NN * HH; j += stride) { g_m[j] = -3.0e38f; g_den[j] = 0.f; }
    for (int j = i; j < 2 * NPAD; j += stride) g_cnt[j] = 0;
    for (int j = i; j < 2 * NN; j += stride) g_pos[j] = 0;
}

// ---------------- dual counting sort (by src AND by dst) ---------------------
__global__ void k_hist(const int* __restrict__ ei) {
    int e = blockIdx.x * blockDim.x + threadIdx.x;
    if (e >= EE) return;
    atomicAdd(&g_cnt[ei[e]], 1);
    atomicAdd(&g_cnt[NPAD + ei[EE + e]], 1);
}

__global__ void k_scanA() {
    __shared__ int sh[256];
    int b = blockIdx.x, t = threadIdx.x;
    int i = b * 256 + t;
    int v = g_cnt[i];
    sh[t] = v;
    __syncthreads();
#pragma unroll
    for (int o = 1; o < 256; o <<= 1) {
        int x = (t >= o) ? sh[t - o] : 0;
        __syncthreads();
        sh[t] += x;
        __syncthreads();
    }
    g_scan[i] = sh[t];
    if (t == 255) g_bsum[b] = sh[255];
}

__global__ void k_scanB() {
    __shared__ int sh[512];
    int t = threadIdx.x;
    int v = (t < NBLK2) ? g_bsum[t] : 0;
    sh[t] = v;
    __syncthreads();
#pragma unroll
    for (int o = 1; o < 512; o <<= 1) {
        int x = (t >= o) ? sh[t - o] : 0;
        __syncthreads();
        sh[t] += x;
        __syncthreads();
    }
    g_bsum[t] = sh[t] - v;   // exclusive block offsets
    if (t == 0) { g_offs[NN] = EE; g_offd[NN] = EE; }
}

__global__ void k_scanC() {
    int i = blockIdx.x * blockDim.x + threadIdx.x;
    if (i >= NN) return;
    g_offs[i] = g_scan[i] - g_cnt[i] + g_bsum[i >> 8];
    int j = NPAD + i;
    g_offd[i] = g_scan[j] - g_cnt[j] + g_bsum[j >> 8] - EE;  // src half sums to EE
}

__global__ void k_scatter(const int* __restrict__ ei) {
    int e = blockIdx.x * blockDim.x + threadIdx.x;
    if (e >= EE) return;
    int s = ei[e];
    int d = ei[EE + e];
    int ps = g_offs[s] + atomicAdd(&g_pos[s], 1);
    gs_src[ps] = s; gs_dst[ps] = d; gs_eid[ps] = e;
    int pd = g_offd[d] + atomicAdd(&g_pos[NN + d], 1);
    gd_src[pd] = s; gd_dst[pd] = d; gd_eid[pd] = e;
}

// ---------------- fused q/k/v GEMM + epilogue -------------------------------
// which==0 (q): write raw qs dense + qt into g_p slot 130
// which==1 (k): write ONLY kt (ks never materialized)
// which==2 (v): write tangent-rescaled v -> g_tan
#define BM 128
#define BK 16
__global__ void __launch_bounds__(256, 2)
k_gemm(const float* __restrict__ x,
       const float* __restrict__ Wq, const float* __restrict__ bq,
       const float* __restrict__ Wk, const float* __restrict__ bk,
       const float* __restrict__ Wv, const float* __restrict__ bv) {
    int which = blockIdx.y >> 2;
    int h = blockIdx.y & 3;
    const float* W = (which == 0) ? Wq : ((which == 1) ? Wk : Wv);
    const float* b = (which == 0) ? bq : ((which == 1) ? bk : bv);
    W += h * DD * KDIM;
    b += h * DD;
    int n0 = blockIdx.x * BM;

    __shared__ float As[BK][BM + 4];
    __shared__ float Bs[BK][DD + 4];
    __shared__ float red[BM][17];
    __shared__ float fac[BM];

    int t = threadIdx.x;
    int tx = t & 15, ty = t >> 4;

    float acc[8][8];
#pragma unroll
    for (int j = 0; j < 8; j++)
#pragma unroll
        for (int c = 0; c < 8; c++) acc[j][c] = 0.f;

    for (int kk = 0; kk < KDIM; kk += BK) {
#pragma unroll
        for (int r = 0; r < 8; r++) {
            int idx = r * 256 + t;
            int m = idx >> 4, k = idx & 15;
            int gi = kk + k, gn = n0 + m;
            float v = 0.f;
            if (gi < KDIM && gn < NN) v = x[(size_t)gn * KDIM + gi];
            As[k][m] = v;
        }
#pragma unroll
        for (int r = 0; r < 8; r++) {
            int idx = r * 256 + t;
            int o = idx >> 4, k = idx & 15;
            int gi = kk + k;
            float v = 0.f;
            if (gi < KDIM) v = W[o * KDIM + gi];
            Bs[k][o] = v;
        }
        __syncthreads();
#pragma unroll
        for (int k = 0; k < BK; k++) {
            float4 a0 = *(const float4*)&As[k][ty * 8];
            float4 a1 = *(const float4*)&As[k][ty * 8 + 4];
            float4 b0 = *(const float4*)&Bs[k][tx * 8];
            float4 b1 = *(const float4*)&Bs[k][tx * 8 + 4];
            float a[8] = {a0.x, a0.y, a0.z, a0.w, a1.x, a1.y, a1.z, a1.w};
            float bb[8] = {b0.x, b0.y, b0.z, b0.w, b1.x, b1.y, b1.z, b1.w};
#pragma unroll
            for (int j = 0; j < 8; j++)
#pragma unroll
                for (int c = 0; c < 8; c++) acc[j][c] = fmaf(a[j], bb[c], acc[j][c]);
        }
        __syncthreads();
    }

#pragma unroll
    for (int c = 0; c < 8; c++) {
        float bb = b[tx * 8 + c];
#pragma unroll
        for (int j = 0; j < 8; j++) acc[j][c] += bb;
    }

#pragma unroll
    for (int j = 0; j < 8; j++) {
        float s = 0.f;
#pragma unroll
        for (int c = 0; c < 8; c++) s = fmaf(acc[j][c], acc[j][c], s);
        red[ty * 8 + j][tx] = s;
    }
    __syncthreads();
    if (t < BM) {
        float ss = 0.f;
#pragma unroll
        for (int i = 0; i < 16; i++) ss += red[t][i];
        int gn = n0 + t;
        if (which == 2) {
            float ns = sqrtf(ss);
            fac[t] = asinhf(ns) / fmaxf(ns, EPSF);
        } else {
            fac[t] = 1.f;
            if (gn < NN) {
                if (which == 0) g_p[((size_t)gn * HH + h) * PST + 130] = sqrtf(ss + 1.0f);
                else            g_kt[gn * HH + h] = sqrtf(ss + 1.0f);
            }
        }
    }
    __syncthreads();

    if (which == 1) return;   // k: only kt needed

#pragma unroll
    for (int j = 0; j < 8; j++) {
        int m = ty * 8 + j;
        int gn = n0 + m;
        if (gn >= NN) continue;
        float f = fac[m];
        float4 v0 = make_float4(acc[j][0] * f, acc[j][1] * f, acc[j][2] * f, acc[j][3] * f);
        float4 v1 = make_float4(acc[j][4] * f, acc[j][5] * f, acc[j][6] * f, acc[j][7] * f);
        float* base = (which == 2) ? (g_tan + ((size_t)gn * HH + h) * DD)
                                   : (g_qs  + ((size_t)gn * HH + h) * DD);
        ((float4*)(base + tx * 8))[0] = v0;
        ((float4*)(base + tx * 8))[1] = v1;
    }
}

// ---------------- p-GEMM: p = Wk^T qs (+ c column) --------------------------
// A = g_qs [node][h][128] dense; B[k][j] = Wk[h][k][j] (j<129), bk[h][k] (j==129)
// out cols 0..129 of g_p (qt at 130 already written by k_gemm)
#define PBN 144           // 16 tx * 9 cols
__global__ void __launch_bounds__(256, 2)
k_pgemm(const float* __restrict__ Wk, const float* __restrict__ bk) {
    int h = blockIdx.y;
    const float* Wh = Wk + h * DD * KDIM;
    const float* bh = bk + h * DD;
    int n0 = blockIdx.x * BM;

    __shared__ float As[BK][BM + 4];
    __shared__ float Bs[BK][PBN + 1];

    int t = threadIdx.x;
    int tx = t & 15, ty = t >> 4;

    float acc[8][9];
#pragma unroll
    for (int j = 0; j < 8; j++)
#pragma unroll
        for (int c = 0; c < 9; c++) acc[j][c] = 0.f;

    for (int kk = 0; kk < DD; kk += BK) {
#pragma unroll
        for (int r = 0; r < 8; r++) {
            int idx = r * 256 + t;
            int m = idx >> 4, k = idx & 15;
            int gn = n0 + m;
            float v = 0.f;
            if (gn < NN) v = g_qs[((size_t)gn * HH + h) * DD + kk + k];
            As[k][m] = v;
        }
        for (int idx = t; idx < BK * 132; idx += 256) {
            int k = idx / 132, j = idx % 132;
            float v = 0.f;
            if (j < KDIM) v = Wh[(kk + k) * KDIM + j];
            else if (j == 129) v = bh[kk + k];
            Bs[k][j] = v;
        }
        // zero pad cols 132..143
        for (int idx = t; idx < BK * 12; idx += 256) {
            int k = idx / 12, j = 132 + idx % 12;
            Bs[k][j] = 0.f;
        }
        __syncthreads();
#pragma unroll
        for (int k = 0; k < BK; k++) {
            float4 a0 = *(const float4*)&As[k][ty * 8];
            float4 a1 = *(const float4*)&As[k][ty * 8 + 4];
            float a[8] = {a0.x, a0.y, a0.z, a0.w, a1.x, a1.y, a1.z, a1.w};
            float bb[9];
#pragma unroll
            for (int c = 0; c < 9; c++) bb[c] = Bs[k][tx * 9 + c];
#pragma unroll
            for (int j = 0; j < 8; j++)
#pragma unroll
                for (int c = 0; c < 9; c++) acc[j][c] = fmaf(a[j], bb[c], acc[j][c]);
        }
        __syncthreads();
    }

#pragma unroll
    for (int j = 0; j < 8; j++) {
        int gn = n0 + ty * 8 + j;
        if (gn >= NN) continue;
        float* op = g_p + ((size_t)gn * HH + h) * PST;
#pragma unroll
        for (int c = 0; c < 9; c++) {
            int col = tx * 9 + c;
            if (col < 130) op[col] = acc[j][c];
        }
    }
}

// ---------------- edge phase ------------------------------------------------
__device__ __forceinline__ void atomicMaxF(float* addr, float v) {
    if (v >= 0.f) atomicMax((int*)addr, __float_as_int(v));
    else          atomicMin((unsigned int*)addr, __float_as_uint(v));
}

// warp per DST-sorted edge: li = p_d . x_s + c - qt*kt  (x/kt L2-resident)
__global__ void k_edge1(const float* __restrict__ x,
                        const float* __restrict__ ef,
                        const float* __restrict__ We) {
    int p = (blockIdx.x * blockDim.x + threadIdx.x) >> 5;
    int lane = threadIdx.x & 31;
    if (p >= EE) return;
    int s = gd_src[p];
    int d = gd_dst[p];
    int e = gd_eid[p];

    const float* xr = x + (size_t)s * KDIM;
    float x0 = __ldg(xr + lane);
    float x1 = __ldg(xr + lane + 32);
    float x2 = __ldg(xr + lane + 64);
    float x3 = __ldg(xr + lane + 96);
    float x4 = (lane == 0) ? __ldg(xr + 128) : 0.f;
    float efl = __ldg(ef + (size_t)e * EDD + lane);

    const float* pb = g_p + (size_t)d * (HH * PST);
    float part[HH];
#pragma unroll
    for (int h = 0; h < HH; h++) {
        const float* ph = pb + h * PST;
        float pp = __ldg(ph + lane) * x0;
        pp = fmaf(__ldg(ph + lane + 32), x1, pp);
        pp = fmaf(__ldg(ph + lane + 64), x2, pp);
        pp = fmaf(__ldg(ph + lane + 96), x3, pp);
        if (lane == 0) pp = fmaf(__ldg(ph + 128), x4, pp);
        pp = fmaf(CHALF * efl, __ldg(We + h * EDD + lane), pp);
        part[h] = pp;
    }
#pragma unroll
    for (int off = 16; off > 0; off >>= 1) {
#pragma unroll
        for (int h = 0; h < HH; h++)
            part[h] += __shfl_xor_sync(0xffffffffu, part[h], off);
    }
    if (lane < HH) {
        int h = lane;
        float c  = __ldg(pb + h * PST + 129);
        float qt = __ldg(pb + h * PST + 130);
        float kt = __ldg(g_kt + (size_t)s * HH + h);
        float li = part[h] + c - qt * kt;
        float logit = (2.f + 2.f * li) * SCALE_INV;
        g_logits[(size_t)e * HH + h] = logit;
        atomicMaxF(&g_m[(size_t)d * HH + h], logit);
    }
}

// thread per (edge, head), original order: exp + denominator
__global__ void k_edge2(const int* __restrict__ ei) {
    int idx = blockIdx.x * blockDim.x + threadIdx.x;
    if (idx >= EE * HH) return;
    int e = idx >> 2, h = idx & 3;
    int d = ei[EE + e];
    float ex = __expf(g_logits[idx] - g_m[(size_t)d * HH + h]);
    g_logits[idx] = ex;
    atomicAdd(&g_den[(size_t)d * HH + h], ex);
}

// warp per SRC-sorted edge: head-fused alpha*tan scatter via red.v4
__global__ void k_edge3() {
    int p = (blockIdx.x * blockDim.x + threadIdx.x) >> 5;
    int lane = threadIdx.x & 31;
    if (p >= EE) return;
    int s = gs_src[p];
    int d = gs_dst[p];
    int e = gs_eid[p];
    float a_l = 0.f;
    if (lane < HH) a_l = g_logits[(size_t)e * HH + lane] /
                         g_den[(size_t)d * HH + lane];
    float alpha[HH];
#pragma unroll
    for (int h = 0; h < HH; h++) alpha[h] = __shfl_sync(0xffffffffu, a_l, h);

    const float4* tb = (const float4*)(g_tan + (size_t)s * (HH * DD));
    float4 t0 = __ldg(tb + lane);
    float4 t1 = __ldg(tb + 32 + lane);
    float4 t2 = __ldg(tb + 64 + lane);
    float4 t3 = __ldg(tb + 96 + lane);
    float cx = alpha[0] * t0.x + alpha[1] * t1.x + alpha[2] * t2.x + alpha[3] * t3.x;
    float cy = alpha[0] * t0.y + alpha[1] * t1.y + alpha[2] * t2.y + alpha[3] * t3.y;
    float cz = alpha[0] * t0.z + alpha[1] * t1.z + alpha[2] * t2.z + alpha[3] * t3.z;
    float cw = alpha[0] * t0.w + alpha[1] * t1.w + alpha[2] * t2.w + alpha[3] * t3.w;
    float* dp = g_agg + (size_t)d * DD + lane * 4;
    asm volatile("red.global.add.v4.f32 [%0], {%1, %2, %3, %4};"
                 :: "l"(dp), "f"(cx), "f"(cy), "f"(cz), "f"(cw) : "memory");
}

// ---------------- output: mean over heads + expmap0 -------------------------
__global__ void k_out(float* __restrict__ out) {
    int w = (blockIdx.x * blockDim.x + threadIdx.x) >> 5;
    int lane = threadIdx.x & 31;
    if (w >= NN) return;
    float4 v = ((const float4*)g_agg)[(size_t)w * 32 + lane];
    float4 ms = make_float4(v.x * 0.25f, v.y * 0.25f, v.z * 0.25f, v.w * 0.25f);
    float ss = ms.x * ms.x + ms.y * ms.y + ms.z * ms.z + ms.w * ms.w;
#pragma unroll
    for (int off = 16; off > 0; off >>= 1) ss += __shfl_xor_sync(0xffffffffu, ss, off);
    float nrm = sqrtf(ss);
    float f = sinhf(nrm) / fmaxf(nrm, EPSF);
    float* op = out + (size_t)w * KDIM;
    if (lane == 0) op[0] = coshf(nrm);
    float* sp = op + 1 + lane * 4;
    sp[0] = f * ms.x; sp[1] = f * ms.y; sp[2] = f * ms.z; sp[3] = f * ms.w;
}

// ---------------------------------------------------------------------------
extern "C" void kernel_launch(void* const* d_in, const int* in_sizes, int n_in,
                              void* d_out, int out_size) {
    const float* x  = (const float*)d_in[0];
    const int*   ei = (const int*)d_in[1];
    const float* ef = (const float*)d_in[2];
    const float* Wq = (const float*)d_in[3];
    const float* bq = (const float*)d_in[4];
    const float* Wk = (const float*)d_in[5];
    const float* bk = (const float*)d_in[6];
    const float* Wv = (const float*)d_in[7];
    const float* bv = (const float*)d_in[8];
    const float* We = (const float*)d_in[9];
    float* out = (float*)d_out;

    k_init<<<2048, 256>>>();
    k_hist<<<(EE + 255) / 256, 256>>>(ei);
    k_scanA<<<NBLK2, 256>>>();
    k_gemm<<<dim3((NN + BM - 1) / BM, 12), 256>>>(x, Wq, bq, Wk, bk, Wv, bv);  // launch #4 (profiled)
    k_scanB<<<1, 512>>>();
    k_scanC<<<(NN + 255) / 256, 256>>>();
    k_scatter<<<(EE + 255) / 256, 256>>>(ei);
    k_pgemm<<<dim3((NN + BM - 1) / BM, HH), 256>>>(Wk, bk);
    k_edge1<<<(EE * 32) / 256, 256>>>(x, ef, We);
    k_edge2<<<(EE * HH + 255) / 256, 256>>>(ei);
    k_edge3<<<(EE * 32) / 256, 256>>>();
    k_out<<<(NN * 32 + 255) / 256, 256>>>(out);
}

// round 8
// speedup vs baseline: 1.2536x; 1.2536x over previous
#include <cuda_runtime.h>
#include <math.h>

// Problem constants
#define NN   50000
#define EE   800000
#define DD   128
#define HH   4
#define EDD  32
#define KDIM 129          // D+1 input dim
#define QKS  132          // per-(n,h) stride for q/k: [space 0..127, time at 128, pad]
#define EPSF 1e-8f
#define SCALE_INV 0.08838834764831845f   // 1/sqrt(128)
#define CHALF     5.656854249492381f     // sqrt(128)/2

#define NPAD 50176        // NN padded to 256 multiple (196 blocks)
#define NBLK 196

// ---------------- scratch (static device globals; no allocation) -------------
__device__ float g_q[NN * HH * QKS];      // 105.6 MB
__device__ float g_k[NN * HH * QKS];      // 105.6 MB
__device__ float g_tan[NN * HH * DD];     // 102.4 MB
__device__ float g_logits[EE * HH];       // 12.8 MB (logits, then exp values)
__device__ float g_m[NN * HH];
__device__ float g_den[NN * HH];
__device__ float g_agg[NN * DD];          // 25.6 MB (head-fused accumulator)
__device__ int   g_cnt[NPAD];
__device__ int   g_scan[NPAD];
__device__ int   g_bsum[256];
__device__ int   g_off[NN + 1];
__device__ int   g_pos[NN];
__device__ int   g_es[EE];                // src, sorted by src
__device__ int   g_ed[EE];                // dst, sorted by src
__device__ int   g_eid[EE];               // original edge id, sorted by src

// ---------------------------------------------------------------------------
__global__ void k_init() {
    int i = blockIdx.x * blockDim.x + threadIdx.x;
    int stride = gridDim.x * blockDim.x;
    for (int j = i; j < NN * DD; j += stride) g_agg[j] = 0.f;
    for (int j = i; j < NN * HH; j += stride) { g_m[j] = -3.0e38f; g_den[j] = 0.f; }
    for (int j = i; j < NPAD; j += stride) g_cnt[j] = 0;
    for (int j = i; j < NN; j += stride) g_pos[j] = 0;
}

// ---------------- counting sort by SRC --------------------------------------
__global__ void k_hist(const int* __restrict__ ei) {
    int e = blockIdx.x * blockDim.x + threadIdx.x;
    if (e >= EE) return;
    atomicAdd(&g_cnt[ei[e]], 1);
}

__global__ void k_scanA() {
    __shared__ int sh[256];
    int b = blockIdx.x, t = threadIdx.x;
    int i = b * 256 + t;
    int v = g_cnt[i];
    sh[t] = v;
    __syncthreads();
#pragma unroll
    for (int o = 1; o < 256; o <<= 1) {
        int x = (t >= o) ? sh[t - o] : 0;
        __syncthreads();
        sh[t] += x;
        __syncthreads();
    }
    g_scan[i] = sh[t];
    if (t == 255) g_bsum[b] = sh[255];
}

__global__ void k_scanB() {
    __shared__ int sh[256];
    int t = threadIdx.x;
    int v = (t < NBLK) ? g_bsum[t] : 0;
    sh[t] = v;
    __syncthreads();
#pragma unroll
    for (int o = 1; o < 256; o <<= 1) {
        int x = (t >= o) ? sh[t - o] : 0;
        __syncthreads();
        sh[t] += x;
        __syncthreads();
    }
    g_bsum[t] = sh[t] - v;   // exclusive
    if (t == 0) g_off[NN] = EE;
}

__global__ void k_scanC() {
    int i = blockIdx.x * blockDim.x + threadIdx.x;
    if (i >= NN) return;
    g_off[i] = g_scan[i] - g_cnt[i] + g_bsum[i >> 8];  // exclusive prefix
}

__global__ void k_scatter(const int* __restrict__ ei) {
    int e = blockIdx.x * blockDim.x + threadIdx.x;
    if (e >= EE) return;
    int s = ei[e];
    int d = ei[EE + e];
    int p = g_off[s] + atomicAdd(&g_pos[s], 1);
    g_es[p] = s;
    g_ed[p] = d;
    g_eid[p] = e;
}

// ---------------- cp.async helpers ------------------------------------------
__device__ __forceinline__ void cpa4(void* dst, const void* src, int sz) {
    unsigned ds = (unsigned)__cvta_generic_to_shared(dst);
    asm volatile("cp.async.ca.shared.global [%0], [%1], 4, %2;"
                 :: "r"(ds), "l"(src), "r"(sz));
}
__device__ __forceinline__ void cpa_commit() {
    asm volatile("cp.async.commit_group;" ::: "memory");
}
__device__ __forceinline__ void cpa_wait0() {
    asm volatile("cp.async.wait_group 0;" ::: "memory");
}

// ---------------- fused q/k/v GEMM + epilogue (double-buffered) --------------
#define BM 128
#define BK 16
#define NIT ((KDIM + BK - 1) / BK)   // 9
__global__ void __launch_bounds__(256, 2)
k_gemm(const float* __restrict__ x,
       const float* __restrict__ Wq, const float* __restrict__ bq,
       const float* __restrict__ Wk, const float* __restrict__ bk,
       const float* __restrict__ Wv, const float* __restrict__ bv) {
    int which = blockIdx.y >> 2;
    int h = blockIdx.y & 3;
    const float* W = (which == 0) ? Wq : ((which == 1) ? Wk : Wv);
    const float* b = (which == 0) ? bq : ((which == 1) ? bk : bv);
    W += h * DD * KDIM;
    b += h * DD;
    int n0 = blockIdx.x * BM;

    __shared__ float As[2][BK][BM + 4];
    __shared__ float Bs[2][BK][DD + 4];
    __shared__ float red[BM][17];
    __shared__ float fac[BM];

    int t = threadIdx.x;
    int tx = t & 15, ty = t >> 4;

    float acc[8][8];
#pragma unroll
    for (int j = 0; j < 8; j++)
#pragma unroll
        for (int c = 0; c < 8; c++) acc[j][c] = 0.f;

    auto issueTile = [&](int kk, int buf) {
#pragma unroll
        for (int r = 0; r < 8; r++) {
            int idx = r * 256 + t;
            int m = idx >> 4, k = idx & 15;
            int gi = kk + k, gn = n0 + m;
            bool ok = (gi < KDIM) && (gn < NN);
            const float* src = ok ? (x + (size_t)gn * KDIM + gi) : x;
            cpa4(&As[buf][k][m], src, ok ? 4 : 0);
        }
#pragma unroll
        for (int r = 0; r < 8; r++) {
            int idx = r * 256 + t;
            int o = idx >> 4, k = idx & 15;
            int gi = kk + k;
            bool ok = (gi < KDIM);
            const float* src = ok ? (W + o * KDIM + gi) : W;
            cpa4(&Bs[buf][k][o], src, ok ? 4 : 0);
        }
        cpa_commit();
    };

    issueTile(0, 0);
    cpa_wait0();
    __syncthreads();

    for (int it = 0; it < NIT; it++) {
        int cur = it & 1;
        if (it + 1 < NIT) issueTile((it + 1) * BK, cur ^ 1);
#pragma unroll
        for (int k = 0; k < BK; k++) {
            float4 a0 = *(const float4*)&As[cur][k][ty * 8];
            float4 a1 = *(const float4*)&As[cur][k][ty * 8 + 4];
            float4 b0 = *(const float4*)&Bs[cur][k][tx * 8];
            float4 b1 = *(const float4*)&Bs[cur][k][tx * 8 + 4];
            float a[8] = {a0.x, a0.y, a0.z, a0.w, a1.x, a1.y, a1.z, a1.w};
            float bb[8] = {b0.x, b0.y, b0.z, b0.w, b1.x, b1.y, b1.z, b1.w};
#pragma unroll
            for (int j = 0; j < 8; j++)
#pragma unroll
                for (int c = 0; c < 8; c++) acc[j][c] = fmaf(a[j], bb[c], acc[j][c]);
        }
        cpa_wait0();
        __syncthreads();
    }

#pragma unroll
    for (int c = 0; c < 8; c++) {
        float bb = b[tx * 8 + c];
#pragma unroll
        for (int j = 0; j < 8; j++) acc[j][c] += bb;
    }

#pragma unroll
    for (int j = 0; j < 8; j++) {
        float s = 0.f;
#pragma unroll
        for (int c = 0; c < 8; c++) s = fmaf(acc[j][c], acc[j][c], s);
        red[ty * 8 + j][tx] = s;
    }
    __syncthreads();
    if (t < BM) {
        float ss = 0.f;
#pragma unroll
        for (int i = 0; i < 16; i++) ss += red[t][i];
        int gn = n0 + t;
        if (which == 2) {
            float ns = sqrtf(ss);
            fac[t] = asinhf(ns) / fmaxf(ns, EPSF);
        } else {
            fac[t] = 1.f;
            if (gn < NN) {
                float* dst = (which == 0) ? g_q : g_k;
                dst[((size_t)gn * HH + h) * QKS + 128] = sqrtf(ss + 1.0f);
            }
        }
    }
    __syncthreads();

#pragma unroll
    for (int j = 0; j < 8; j++) {
        int m = ty * 8 + j;
        int gn = n0 + m;
        if (gn >= NN) continue;
        float f = fac[m];
        float4 v0 = make_float4(acc[j][0] * f, acc[j][1] * f, acc[j][2] * f, acc[j][3] * f);
        float4 v1 = make_float4(acc[j][4] * f, acc[j][5] * f, acc[j][6] * f, acc[j][7] * f);
        float* base;
        if (which == 2) base = g_tan + ((size_t)gn * HH + h) * DD;
        else            base = ((which == 0) ? g_q : g_k) + ((size_t)gn * HH + h) * QKS;
        ((float4*)(base + tx * 8))[0] = v0;
        ((float4*)(base + tx * 8))[1] = v1;
    }
}

// ---------------- edge phase (edges sorted by src) ---------------------------
__device__ __forceinline__ void atomicMaxF(float* addr, float v) {
    if (v >= 0.f) atomicMax((int*)addr, __float_as_int(v));
    else          atomicMin((unsigned int*)addr, __float_as_uint(v));
}

// warp per sorted edge: logits for 4 heads; k[src] L1/L2-cached via sort.
__global__ void k_edge1(const float* __restrict__ ef,
                        const float* __restrict__ We) {
    int p = (blockIdx.x * blockDim.x + threadIdx.x) >> 5;
    int lane = threadIdx.x & 31;
    if (p >= EE) return;
    int s = g_es[p];
    int d = g_ed[p];
    int e = g_eid[p];
    float efl = __ldg(ef + (size_t)e * EDD + lane);

    const float* qb = g_q + (size_t)d * (HH * QKS);
    const float* kb = g_k + (size_t)s * (HH * QKS);
    float part[HH];
#pragma unroll
    for (int h = 0; h < HH; h++) {
        const float* qh = qb + h * QKS;
        const float* kh = kb + h * QKS;
        float4 q4 = __ldg((const float4*)qh + lane);
        float4 k4 = __ldg((const float4*)kh + lane);
        float pp = q4.x * k4.x + q4.y * k4.y + q4.z * k4.z + q4.w * k4.w;
        if (lane == 0) pp = fmaf(-__ldg(qh + 128), __ldg(kh + 128), pp);
        pp = fmaf(CHALF * efl, __ldg(We + h * EDD + lane), pp);
        part[h] = pp;
    }
#pragma unroll
    for (int off = 16; off > 0; off >>= 1) {
#pragma unroll
        for (int h = 0; h < HH; h++)
            part[h] += __shfl_xor_sync(0xffffffffu, part[h], off);
    }
    if (lane < HH) {
        float logit = (2.f + 2.f * part[lane]) * SCALE_INV;
        g_logits[(size_t)p * HH + lane] = logit;
        atomicMaxF(&g_m[(size_t)d * HH + lane], logit);
    }
}

// thread per (sorted-edge, head): exp + denominator
__global__ void k_edge2() {
    int idx = blockIdx.x * blockDim.x + threadIdx.x;
    if (idx >= EE * HH) return;
    int p = idx >> 2, h = idx & 3;
    int d = g_ed[p];
    float ex = __expf(g_logits[idx] - g_m[(size_t)d * HH + h]);
    g_logits[idx] = ex;
    atomicAdd(&g_den[(size_t)d * HH + h], ex);
}

// warp per src-sorted edge: head-fused alpha*tan scatter via red.v4
__global__ void k_edge3() {
    int p = (blockIdx.x * blockDim.x + threadIdx.x) >> 5;
    int lane = threadIdx.x & 31;
    if (p >= EE) return;
    int s = g_es[p];
    int d = g_ed[p];
    float a_l = 0.f;
    if (lane < HH) a_l = g_logits[(size_t)p * HH + lane] /
                         g_den[(size_t)d * HH + lane];
    float alpha[HH];
#pragma unroll
    for (int h = 0; h < HH; h++) alpha[h] = __shfl_sync(0xffffffffu, a_l, h);

    const float4* tb = (const float4*)(g_tan + (size_t)s * (HH * DD));
    float4 t0 = __ldg(tb + lane);
    float4 t1 = __ldg(tb + 32 + lane);
    float4 t2 = __ldg(tb + 64 + lane);
    float4 t3 = __ldg(tb + 96 + lane);
    float cx = alpha[0] * t0.x + alpha[1] * t1.x + alpha[2] * t2.x + alpha[3] * t3.x;
    float cy = alpha[0] * t0.y + alpha[1] * t1.y + alpha[2] * t2.y + alpha[3] * t3.y;
    float cz = alpha[0] * t0.z + alpha[1] * t1.z + alpha[2] * t2.z + alpha[3] * t3.z;
    float cw = alpha[0] * t0.w + alpha[1] * t1.w + alpha[2] * t2.w + alpha[3] * t3.w;
    float* dp = g_agg + (size_t)d * DD + lane * 4;
    asm volatile("red.global.add.v4.f32 [%0], {%1, %2, %3, %4};"
                 :: "l"(dp), "f"(cx), "f"(cy), "f"(cz), "f"(cw) : "memory");
}

// ---------------- output: mean over heads + expmap0 -------------------------
__global__ void k_out(float* __restrict__ out) {
    int w = (blockIdx.x * blockDim.x + threadIdx.x) >> 5;
    int lane = threadIdx.x & 31;
    if (w >= NN) return;
    float4 v = ((const float4*)g_agg)[(size_t)w * 32 + lane];
    float4 ms = make_float4(v.x * 0.25f, v.y * 0.25f, v.z * 0.25f, v.w * 0.25f);
    float ss = ms.x * ms.x + ms.y * ms.y + ms.z * ms.z + ms.w * ms.w;
#pragma unroll
    for (int off = 16; off > 0; off >>= 1) ss += __shfl_xor_sync(0xffffffffu, ss, off);
    float nrm = sqrtf(ss);
    float f = sinhf(nrm) / fmaxf(nrm, EPSF);
    float* op = out + (size_t)w * KDIM;
    if (lane == 0) op[0] = coshf(nrm);
    float* sp = op + 1 + lane * 4;
    sp[0] = f * ms.x; sp[1] = f * ms.y; sp[2] = f * ms.z; sp[3] = f * ms.w;
}

// ---------------------------------------------------------------------------
extern "C" void kernel_launch(void* const* d_in, const int* in_sizes, int n_in,
                              void* d_out, int out_size) {
    const float* x  = (const float*)d_in[0];
    const int*   ei = (const int*)d_in[1];
    const float* ef = (const float*)d_in[2];
    const float* Wq = (const float*)d_in[3];
    const float* bq = (const float*)d_in[4];
    const float* Wk = (const float*)d_in[5];
    const float* bk = (const float*)d_in[6];
    const float* Wv = (const float*)d_in[7];
    const float* bv = (const float*)d_in[8];
    const float* We = (const float*)d_in[9];
    float* out = (float*)d_out;

    k_init<<<2048, 256>>>();
    k_hist<<<(EE + 255) / 256, 256>>>(ei);
    k_scanA<<<NBLK, 256>>>();
    k_gemm<<<dim3((NN + BM - 1) / BM, 12), 256>>>(x, Wq, bq, Wk, bk, Wv, bv);  // 4th launch (profiled)
    k_scanB<<<1, 256>>>();
    k_scanC<<<(NN + 255) / 256, 256>>>();
    k_scatter<<<(EE + 255) / 256, 256>>>(ei);
    k_edge1<<<(EE * 32) / 256, 256>>>(ef, We);
    k_edge2<<<(EE * HH + 255) / 256, 256>>>();
    k_edge3<<<(EE * 32) / 256, 256>>>();
    k_out<<<(NN * 32 + 255) / 256, 256>>>(out);
}

// round 9
// speedup vs baseline: 1.3531x; 1.0793x over previous
#include <cuda_runtime.h>
#include <math.h>

// Problem constants
#define NN   50000
#define EE   800000
#define DD   128
#define HH   4
#define EDD  32
#define KDIM 129          // D+1 input dim
#define QKS  132          // per-(n,h) stride for q/k: [space 0..127, time at 128, pad]
#define EPSF 1e-8f
#define SCALE_INV 0.08838834764831845f   // 1/sqrt(128)
#define CHALF     5.656854249492381f     // sqrt(128)/2

#define NPAD 50176        // NN padded to 256 multiple (196 blocks)
#define NBLK 196

// ---------------- scratch (static device globals; no allocation) -------------
__device__ float g_q[NN * HH * QKS];      // 105.6 MB
__device__ float g_k[NN * HH * QKS];      // 105.6 MB
__device__ float g_tan[NN * HH * DD];     // 102.4 MB
__device__ float g_logits[EE * HH];       // 12.8 MB (logits, then exp values)
__device__ float g_m[NN * HH];
__device__ float g_den[NN * HH];
__device__ float g_agg[NN * DD];          // 25.6 MB (head-fused accumulator)
__device__ int   g_cnt[NPAD];
__device__ int   g_scan[NPAD];
__device__ int   g_bsum[256];
__device__ int   g_off[NN + 1];
__device__ int   g_pos[NN];
__device__ int   g_es[EE];                // src, sorted by src
__device__ int   g_ed[EE];                // dst, sorted by src
__device__ int   g_eid[EE];               // original edge id, sorted by src

// ---------------------------------------------------------------------------
__global__ void k_init() {
    int i = blockIdx.x * blockDim.x + threadIdx.x;
    int stride = gridDim.x * blockDim.x;
    for (int j = i; j < NN * DD; j += stride) g_agg[j] = 0.f;
    for (int j = i; j < NN * HH; j += stride) { g_m[j] = -3.0e38f; g_den[j] = 0.f; }
    for (int j = i; j < NPAD; j += stride) g_cnt[j] = 0;
    for (int j = i; j < NN; j += stride) g_pos[j] = 0;
}

// ---------------- counting sort by SRC --------------------------------------
__global__ void k_hist(const int* __restrict__ ei) {
    int e = blockIdx.x * blockDim.x + threadIdx.x;
    if (e >= EE) return;
    atomicAdd(&g_cnt[ei[e]], 1);
}

__global__ void k_scanA() {
    __shared__ int sh[256];
    int b = blockIdx.x, t = threadIdx.x;
    int i = b * 256 + t;
    int v = g_cnt[i];
    sh[t] = v;
    __syncthreads();
#pragma unroll
    for (int o = 1; o < 256; o <<= 1) {
        int x = (t >= o) ? sh[t - o] : 0;
        __syncthreads();
        sh[t] += x;
        __syncthreads();
    }
    g_scan[i] = sh[t];
    if (t == 255) g_bsum[b] = sh[255];
}

__global__ void k_scanB() {
    __shared__ int sh[256];
    int t = threadIdx.x;
    int v = (t < NBLK) ? g_bsum[t] : 0;
    sh[t] = v;
    __syncthreads();
#pragma unroll
    for (int o = 1; o < 256; o <<= 1) {
        int x = (t >= o) ? sh[t - o] : 0;
        __syncthreads();
        sh[t] += x;
        __syncthreads();
    }
    g_bsum[t] = sh[t] - v;   // exclusive
    if (t == 0) g_off[NN] = EE;
}

__global__ void k_scanC() {
    int i = blockIdx.x * blockDim.x + threadIdx.x;
    if (i >= NN) return;
    g_off[i] = g_scan[i] - g_cnt[i] + g_bsum[i >> 8];  // exclusive prefix
}

__global__ void k_scatter(const int* __restrict__ ei) {
    int e = blockIdx.x * blockDim.x + threadIdx.x;
    if (e >= EE) return;
    int s = ei[e];
    int d = ei[EE + e];
    int p = g_off[s] + atomicAdd(&g_pos[s], 1);
    g_es[p] = s;
    g_ed[p] = d;
    g_eid[p] = e;
}

// ---------------- cp.async helpers ------------------------------------------
__device__ __forceinline__ void cpa4(void* dst, const void* src, int sz) {
    unsigned ds = (unsigned)__cvta_generic_to_shared(dst);
    asm volatile("cp.async.ca.shared.global [%0], [%1], 4, %2;"
                 :: "r"(ds), "l"(src), "r"(sz));
}
__device__ __forceinline__ void cpa_commit() {
    asm volatile("cp.async.commit_group;" ::: "memory");
}
__device__ __forceinline__ void cpa_wait0() {
    asm volatile("cp.async.wait_group 0;" ::: "memory");
}

// ---------------- fused q/k/v GEMM + epilogue (double-buffered) --------------
// Thread tile: rows {ty*8..ty*8+7}, cols {tx*4..tx*4+3} u {64+tx*4..64+tx*4+3}
// B-side LDS is conflict-free: per 8-thread phase, float4 @ tx*4 covers 128
// contiguous bytes.
#define BM 128
#define BK 16
#define NIT ((KDIM + BK - 1) / BK)   // 9
__global__ void __launch_bounds__(256, 2)
k_gemm(const float* __restrict__ x,
       const float* __restrict__ Wq, const float* __restrict__ bq,
       const float* __restrict__ Wk, const float* __restrict__ bk,
       const float* __restrict__ Wv, const float* __restrict__ bv) {
    int which = blockIdx.y >> 2;
    int h = blockIdx.y & 3;
    const float* W = (which == 0) ? Wq : ((which == 1) ? Wk : Wv);
    const float* b = (which == 0) ? bq : ((which == 1) ? bk : bv);
    W += h * DD * KDIM;
    b += h * DD;
    int n0 = blockIdx.x * BM;

    __shared__ float As[2][BK][BM + 4];
    __shared__ float Bs[2][BK][DD + 4];
    __shared__ float red[BM][17];
    __shared__ float fac[BM];

    int t = threadIdx.x;
    int tx = t & 15, ty = t >> 4;

    float acc[8][8];   // [row j][c: 0-3 -> tx*4+c, 4-7 -> 64+tx*4+(c-4)]
#pragma unroll
    for (int j = 0; j < 8; j++)
#pragma unroll
        for (int c = 0; c < 8; c++) acc[j][c] = 0.f;

    auto issueTile = [&](int kk, int buf) {
#pragma unroll
        for (int r = 0; r < 8; r++) {
            int idx = r * 256 + t;
            int m = idx >> 4, k = idx & 15;
            int gi = kk + k, gn = n0 + m;
            bool ok = (gi < KDIM) && (gn < NN);
            const float* src = ok ? (x + (size_t)gn * KDIM + gi) : x;
            cpa4(&As[buf][k][m], src, ok ? 4 : 0);
        }
#pragma unroll
        for (int r = 0; r < 8; r++) {
            int idx = r * 256 + t;
            int o = idx >> 4, k = idx & 15;
            int gi = kk + k;
            bool ok = (gi < KDIM);
            const float* src = ok ? (W + o * KDIM + gi) : W;
            cpa4(&Bs[buf][k][o], src, ok ? 4 : 0);
        }
        cpa_commit();
    };

    issueTile(0, 0);
    cpa_wait0();
    __syncthreads();

    for (int it = 0; it < NIT; it++) {
        int cur = it & 1;
        if (it + 1 < NIT) issueTile((it + 1) * BK, cur ^ 1);
#pragma unroll
        for (int k = 0; k < BK; k++) {
            float4 a0 = *(const float4*)&As[cur][k][ty * 8];
            float4 a1 = *(const float4*)&As[cur][k][ty * 8 + 4];
            float4 b0 = *(const float4*)&Bs[cur][k][tx * 4];        // conflict-free
            float4 b1 = *(const float4*)&Bs[cur][k][64 + tx * 4];   // conflict-free
            float a[8] = {a0.x, a0.y, a0.z, a0.w, a1.x, a1.y, a1.z, a1.w};
            float bb[8] = {b0.x, b0.y, b0.z, b0.w, b1.x, b1.y, b1.z, b1.w};
#pragma unroll
            for (int j = 0; j < 8; j++)
#pragma unroll
                for (int c = 0; c < 8; c++) acc[j][c] = fmaf(a[j], bb[c], acc[j][c]);
        }
        cpa_wait0();
        __syncthreads();
    }

    // add bias
#pragma unroll
    for (int c = 0; c < 4; c++) {
        float bl = b[tx * 4 + c];
        float bh = b[64 + tx * 4 + c];
#pragma unroll
        for (int j = 0; j < 8; j++) { acc[j][c] += bl; acc[j][c + 4] += bh; }
    }

    // per-node sum of squares across the 16 tx threads
#pragma unroll
    for (int j = 0; j < 8; j++) {
        float s = 0.f;
#pragma unroll
        for (int c = 0; c < 8; c++) s = fmaf(acc[j][c], acc[j][c], s);
        red[ty * 8 + j][tx] = s;
    }
    __syncthreads();
    if (t < BM) {
        float ss = 0.f;
#pragma unroll
        for (int i = 0; i < 16; i++) ss += red[t][i];
        int gn = n0 + t;
        if (which == 2) {
            float ns = sqrtf(ss);
            fac[t] = asinhf(ns) / fmaxf(ns, EPSF);
        } else {
            fac[t] = 1.f;
            if (gn < NN) {
                float* dst = (which == 0) ? g_q : g_k;
                dst[((size_t)gn * HH + h) * QKS + 128] = sqrtf(ss + 1.0f);
            }
        }
    }
    __syncthreads();

    // write space components: cols tx*4.. and 64+tx*4..
#pragma unroll
    for (int j = 0; j < 8; j++) {
        int m = ty * 8 + j;
        int gn = n0 + m;
        if (gn >= NN) continue;
        float f = fac[m];
        float4 v0 = make_float4(acc[j][0] * f, acc[j][1] * f, acc[j][2] * f, acc[j][3] * f);
        float4 v1 = make_float4(acc[j][4] * f, acc[j][5] * f, acc[j][6] * f, acc[j][7] * f);
        float* base;
        if (which == 2) base = g_tan + ((size_t)gn * HH + h) * DD;
        else            base = ((which == 0) ? g_q : g_k) + ((size_t)gn * HH + h) * QKS;
        *(float4*)(base + tx * 4) = v0;
        *(float4*)(base + 64 + tx * 4) = v1;
    }
}

// ---------------- edge phase (edges sorted by src) ---------------------------
__device__ __forceinline__ void atomicMaxF(float* addr, float v) {
    if (v >= 0.f) atomicMax((int*)addr, __float_as_int(v));
    else          atomicMin((unsigned int*)addr, __float_as_uint(v));
}

// warp per sorted edge: logits for 4 heads; k[src] L1/L2-cached via sort.
__global__ void k_edge1(const float* __restrict__ ef,
                        const float* __restrict__ We) {
    int p = (blockIdx.x * blockDim.x + threadIdx.x) >> 5;
    int lane = threadIdx.x & 31;
    if (p >= EE) return;
    int s = g_es[p];
    int d = g_ed[p];
    int e = g_eid[p];
    float efl = __ldg(ef + (size_t)e * EDD + lane);

    const float* qb = g_q + (size_t)d * (HH * QKS);
    const float* kb = g_k + (size_t)s * (HH * QKS);
    float part[HH];
#pragma unroll
    for (int h = 0; h < HH; h++) {
        const float* qh = qb + h * QKS;
        const float* kh = kb + h * QKS;
        float4 q4 = __ldg((const float4*)qh + lane);
        float4 k4 = __ldg((const float4*)kh + lane);
        float pp = q4.x * k4.x + q4.y * k4.y + q4.z * k4.z + q4.w * k4.w;
        if (lane == 0) pp = fmaf(-__ldg(qh + 128), __ldg(kh + 128), pp);
        pp = fmaf(CHALF * efl, __ldg(We + h * EDD + lane), pp);
        part[h] = pp;
    }
#pragma unroll
    for (int off = 16; off > 0; off >>= 1) {
#pragma unroll
        for (int h = 0; h < HH; h++)
            part[h] += __shfl_xor_sync(0xffffffffu, part[h], off);
    }
    if (lane < HH) {
        float logit = (2.f + 2.f * part[lane]) * SCALE_INV;
        g_logits[(size_t)p * HH + lane] = logit;
        atomicMaxF(&g_m[(size_t)d * HH + lane], logit);
    }
}

// thread per (sorted-edge, head): exp + denominator
__global__ void k_edge2() {
    int idx = blockIdx.x * blockDim.x + threadIdx.x;
    if (idx >= EE * HH) return;
    int p = idx >> 2, h = idx & 3;
    int d = g_ed[p];
    float ex = __expf(g_logits[idx] - g_m[(size_t)d * HH + h]);
    g_logits[idx] = ex;
    atomicAdd(&g_den[(size_t)d * HH + h], ex);
}

// warp per src-sorted edge: head-fused alpha*tan scatter via red.v4
__global__ void k_edge3() {
    int p = (blockIdx.x * blockDim.x + threadIdx.x) >> 5;
    int lane = threadIdx.x & 31;
    if (p >= EE) return;
    int s = g_es[p];
    int d = g_ed[p];
    float a_l = 0.f;
    if (lane < HH) a_l = g_logits[(size_t)p * HH + lane] /
                         g_den[(size_t)d * HH + lane];
    float alpha[HH];
#pragma unroll
    for (int h = 0; h < HH; h++) alpha[h] = __shfl_sync(0xffffffffu, a_l, h);

    const float4* tb = (const float4*)(g_tan + (size_t)s * (HH * DD));
    float4 t0 = __ldg(tb + lane);
    float4 t1 = __ldg(tb + 32 + lane);
    float4 t2 = __ldg(tb + 64 + lane);
    float4 t3 = __ldg(tb + 96 + lane);
    float cx = alpha[0] * t0.x + alpha[1] * t1.x + alpha[2] * t2.x + alpha[3] * t3.x;
    float cy = alpha[0] * t0.y + alpha[1] * t1.y + alpha[2] * t2.y + alpha[3] * t3.y;
    float cz = alpha[0] * t0.z + alpha[1] * t1.z + alpha[2] * t2.z + alpha[3] * t3.z;
    float cw = alpha[0] * t0.w + alpha[1] * t1.w + alpha[2] * t2.w + alpha[3] * t3.w;
    float* dp = g_agg + (size_t)d * DD + lane * 4;
    asm volatile("red.global.add.v4.f32 [%0], {%1, %2, %3, %4};"
                 :: "l"(dp), "f"(cx), "f"(cy), "f"(cz), "f"(cw) : "memory");
}

// ---------------- output: mean over heads + expmap0 -------------------------
__global__ void k_out(float* __restrict__ out) {
    int w = (blockIdx.x * blockDim.x + threadIdx.x) >> 5;
    int lane = threadIdx.x & 31;
    if (w >= NN) return;
    float4 v = ((const float4*)g_agg)[(size_t)w * 32 + lane];
    float4 ms = make_float4(v.x * 0.25f, v.y * 0.25f, v.z * 0.25f, v.w * 0.25f);
    float ss = ms.x * ms.x + ms.y * ms.y + ms.z * ms.z + ms.w * ms.w;
#pragma unroll
    for (int off = 16; off > 0; off >>= 1) ss += __shfl_xor_sync(0xffffffffu, ss, off);
    float nrm = sqrtf(ss);
    float f = sinhf(nrm) / fmaxf(nrm, EPSF);
    float* op = out + (size_t)w * KDIM;
    if (lane == 0) op[0] = coshf(nrm);
    float* sp = op + 1 + lane * 4;
    sp[0] = f * ms.x; sp[1] = f * ms.y; sp[2] = f * ms.z; sp[3] = f * ms.w;
}

// ---------------------------------------------------------------------------
extern "C" void kernel_launch(void* const* d_in, const int* in_sizes, int n_in,
                              void* d_out, int out_size) {
    const float* x  = (const float*)d_in[0];
    const int*   ei = (const int*)d_in[1];
    const float* ef = (const float*)d_in[2];
    const float* Wq = (const float*)d_in[3];
    const float* bq = (const float*)d_in[4];
    const float* Wk = (const float*)d_in[5];
    const float* bk = (const float*)d_in[6];
    const float* Wv = (const float*)d_in[7];
    const float* bv = (const float*)d_in[8];
    const float* We = (const float*)d_in[9];
    float* out = (float*)d_out;

    k_init<<<2048, 256>>>();
    k_hist<<<(EE + 255) / 256, 256>>>(ei);
    k_scanA<<<NBLK, 256>>>();
    k_gemm<<<dim3((NN + BM - 1) / BM, 12), 256>>>(x, Wq, bq, Wk, bk, Wv, bv);  // 4th launch (profiled)
    k_scanB<<<1, 256>>>();
    k_scanC<<<(NN + 255) / 256, 256>>>();
    k_scatter<<<(EE + 255) / 256, 256>>>(ei);
    k_edge1<<<(EE * 32) / 256, 256>>>(ef, We);
    k_edge2<<<(EE * HH + 255) / 256, 256>>>();
    k_edge3<<<(EE * 32) / 256, 256>>>();
    k_out<<<(NN * 32 + 255) / 256, 256>>>(out);
}

// round 10
// speedup vs baseline: 1.4212x; 1.0503x over previous
#include <cuda_runtime.h>
#include <math.h>

// Problem constants
#define NN   50000
#define EE   800000
#define DD   128
#define HH   4
#define EDD  32
#define KDIM 129          // D+1 input dim
#define QKS  132          // per-(n,h) stride for q/k: [space 0..127, time at 128, pad]
#define EPSF 1e-8f
#define SCALE_INV 0.08838834764831845f   // 1/sqrt(128)
#define CHALF     5.656854249492381f     // sqrt(128)/2

#define NPAD 50176        // NN padded to 256 multiple (196 blocks)
#define NBLK 196

// ---------------- scratch (static device globals; no allocation) -------------
__device__ float g_q[NN * HH * QKS];      // 105.6 MB
__device__ float g_k[NN * HH * QKS];      // 105.6 MB
__device__ float g_tan[NN * HH * DD];     // 102.4 MB
__device__ float g_logits[EE * HH];       // 12.8 MB (logits, then exp values)
__device__ float g_m[NN * HH];
__device__ float g_den[NN * HH];
__device__ float g_agg[NN * DD];          // 25.6 MB (head-fused accumulator)
__device__ int   g_cnt[NPAD];
__device__ int   g_scan[NPAD];
__device__ int   g_bsum[256];
__device__ int   g_off[NN + 1];
__device__ int   g_pos[NN];
__device__ int   g_es[EE];                // src, sorted by src
__device__ int   g_ed[EE];                // dst, sorted by src
__device__ int   g_eid[EE];               // original edge id, sorted by src

// ---------------------------------------------------------------------------
__global__ void k_init() {
    int i = blockIdx.x * blockDim.x + threadIdx.x;
    int stride = gridDim.x * blockDim.x;
    for (int j = i; j < NN * DD; j += stride) g_agg[j] = 0.f;
    for (int j = i; j < NN * HH; j += stride) { g_m[j] = -3.0e38f; g_den[j] = 0.f; }
    for (int j = i; j < NPAD; j += stride) g_cnt[j] = 0;
    for (int j = i; j < NN; j += stride) g_pos[j] = 0;
}

// ---------------- counting sort by SRC --------------------------------------
__global__ void k_hist(const int* __restrict__ ei) {
    int e = blockIdx.x * blockDim.x + threadIdx.x;
    if (e >= EE) return;
    atomicAdd(&g_cnt[ei[e]], 1);
}

__global__ void k_scanA() {
    __shared__ int sh[256];
    int b = blockIdx.x, t = threadIdx.x;
    int i = b * 256 + t;
    int v = g_cnt[i];
    sh[t] = v;
    __syncthreads();
#pragma unroll
    for (int o = 1; o < 256; o <<= 1) {
        int x = (t >= o) ? sh[t - o] : 0;
        __syncthreads();
        sh[t] += x;
        __syncthreads();
    }
    g_scan[i] = sh[t];
    if (t == 255) g_bsum[b] = sh[255];
}

__global__ void k_scanB() {
    __shared__ int sh[256];
    int t = threadIdx.x;
    int v = (t < NBLK) ? g_bsum[t] : 0;
    sh[t] = v;
    __syncthreads();
#pragma unroll
    for (int o = 1; o < 256; o <<= 1) {
        int x = (t >= o) ? sh[t - o] : 0;
        __syncthreads();
        sh[t] += x;
        __syncthreads();
    }
    g_bsum[t] = sh[t] - v;   // exclusive
    if (t == 0) g_off[NN] = EE;
}

__global__ void k_scanC() {
    int i = blockIdx.x * blockDim.x + threadIdx.x;
    if (i >= NN) return;
    g_off[i] = g_scan[i] - g_cnt[i] + g_bsum[i >> 8];  // exclusive prefix
}

__global__ void k_scatter(const int* __restrict__ ei) {
    int e = blockIdx.x * blockDim.x + threadIdx.x;
    if (e >= EE) return;
    int s = ei[e];
    int d = ei[EE + e];
    int p = g_off[s] + atomicAdd(&g_pos[s], 1);
    g_es[p] = s;
    g_ed[p] = d;
    g_eid[p] = e;
}

// ---------------- cp.async helpers ------------------------------------------
__device__ __forceinline__ void cpa4(void* dst, const void* src, int sz) {
    unsigned ds = (unsigned)__cvta_generic_to_shared(dst);
    asm volatile("cp.async.ca.shared.global [%0], [%1], 4, %2;"
                 :: "r"(ds), "l"(src), "r"(sz));
}
__device__ __forceinline__ void cpa_commit() {
    asm volatile("cp.async.commit_group;" ::: "memory");
}
__device__ __forceinline__ void cpa_wait0() {
    asm volatile("cp.async.wait_group 0;" ::: "memory");
}

// ---------------- tf32 split + mma helpers ----------------------------------
__device__ __forceinline__ void split_tf32(float v, unsigned& hi, unsigned& lo) {
    asm("cvt.rna.tf32.f32 %0, %1;" : "=r"(hi) : "f"(v));
    float l = v - __uint_as_float(hi);
    asm("cvt.rna.tf32.f32 %0, %1;" : "=r"(lo) : "f"(l));
}
__device__ __forceinline__ void mma8(float* c, const unsigned* a, unsigned b0, unsigned b1) {
    asm volatile("mma.sync.aligned.m16n8k8.row.col.f32.tf32.tf32.f32 "
                 "{%0,%1,%2,%3}, {%4,%5,%6,%7}, {%8,%9}, {%0,%1,%2,%3};"
                 : "+f"(c[0]), "+f"(c[1]), "+f"(c[2]), "+f"(c[3])
                 : "r"(a[0]), "r"(a[1]), "r"(a[2]), "r"(a[3]), "r"(b0), "r"(b1));
}

// ---------------- fused q/k/v GEMM via 3xTF32 tensor-core mma ----------------
// Block tile 128(M nodes) x 128(N outputs), 8 warps (4m x 2n), warp 32x64.
// smem tiles row-major [row][20] -> all fragment LDS phases conflict-free.
#define BM 128
#define BK 16
#define NIT ((KDIM + BK - 1) / BK)   // 9 (K padded to 144 with zeros)
__global__ void __launch_bounds__(256, 2)
k_gemm(const float* __restrict__ x,
       const float* __restrict__ Wq, const float* __restrict__ bq,
       const float* __restrict__ Wk, const float* __restrict__ bk,
       const float* __restrict__ Wv, const float* __restrict__ bv) {
    int which = blockIdx.y >> 2;
    int h = blockIdx.y & 3;
    const float* W = (which == 0) ? Wq : ((which == 1) ? Wk : Wv);
    const float* b = (which == 0) ? bq : ((which == 1) ? bk : bv);
    W += h * DD * KDIM;
    b += h * DD;
    int n0 = blockIdx.x * BM;

    __shared__ float As[2][BM][20];   // [node row][k 0..15, pad 20]
    __shared__ float Bs[2][DD][20];   // [out col][k 0..15, pad 20]
    __shared__ float red2[BM][2];
    __shared__ float fac[BM];

    int t = threadIdx.x;
    int wid = t >> 5, lane = t & 31;
    int wm = wid & 3, wn = wid >> 2;      // warp grid 4(m) x 2(n)
    int g = lane >> 2, q = lane & 3;

    float C[2][8][4];
#pragma unroll
    for (int mf = 0; mf < 2; mf++)
#pragma unroll
        for (int nf = 0; nf < 8; nf++)
#pragma unroll
            for (int c = 0; c < 4; c++) C[mf][nf][c] = 0.f;

    auto issueTile = [&](int kk, int buf) {
#pragma unroll
        for (int r = 0; r < 8; r++) {
            int idx = r * 256 + t;
            int m = idx >> 4, k = idx & 15;
            int gi = kk + k, gn = n0 + m;
            bool ok = (gi < KDIM) && (gn < NN);
            const float* src = ok ? (x + (size_t)gn * KDIM + gi) : x;
            cpa4(&As[buf][m][k], src, ok ? 4 : 0);
        }
#pragma unroll
        for (int r = 0; r < 8; r++) {
            int idx = r * 256 + t;
            int o = idx >> 4, k = idx & 15;
            int gi = kk + k;
            bool ok = (gi < KDIM);
            const float* src = ok ? (W + o * KDIM + gi) : W;
            cpa4(&Bs[buf][o][k], src, ok ? 4 : 0);
        }
        cpa_commit();
    };

    issueTile(0, 0);
    cpa_wait0();
    __syncthreads();

    for (int it = 0; it < NIT; it++) {
        int cur = it & 1;
        if (it + 1 < NIT) issueTile((it + 1) * BK, cur ^ 1);
#pragma unroll
        for (int ks = 0; ks < 2; ks++) {
            int kb = ks * 8;
            unsigned ah[2][4], al[2][4];
#pragma unroll
            for (int mf = 0; mf < 2; mf++) {
                int m0 = wm * 32 + mf * 16 + g;
                float a0 = As[cur][m0][kb + q];
                float a1 = As[cur][m0 + 8][kb + q];
                float a2 = As[cur][m0][kb + q + 4];
                float a3 = As[cur][m0 + 8][kb + q + 4];
                split_tf32(a0, ah[mf][0], al[mf][0]);
                split_tf32(a1, ah[mf][1], al[mf][1]);
                split_tf32(a2, ah[mf][2], al[mf][2]);
                split_tf32(a3, ah[mf][3], al[mf][3]);
            }
#pragma unroll
            for (int nf = 0; nf < 8; nf++) {
                int nc = wn * 64 + nf * 8 + g;
                float b0 = Bs[cur][nc][kb + q];
                float b1 = Bs[cur][nc][kb + q + 4];
                unsigned bh0, bl0, bh1, bl1;
                split_tf32(b0, bh0, bl0);
                split_tf32(b1, bh1, bl1);
#pragma unroll
                for (int mf = 0; mf < 2; mf++) {
                    mma8(C[mf][nf], ah[mf], bh0, bh1);   // hi*hi
                    mma8(C[mf][nf], ah[mf], bl0, bl1);   // hi*lo
                    mma8(C[mf][nf], al[mf], bh0, bh1);   // lo*hi
                }
            }
        }
        cpa_wait0();
        __syncthreads();
    }

    // bias (before row-norm, per reference)
#pragma unroll
    for (int nf = 0; nf < 8; nf++) {
        int col = wn * 64 + nf * 8 + q * 2;
        float b0 = __ldg(b + col);
        float b1 = __ldg(b + col + 1);
#pragma unroll
        for (int mf = 0; mf < 2; mf++) {
            C[mf][nf][0] += b0; C[mf][nf][1] += b1;
            C[mf][nf][2] += b0; C[mf][nf][3] += b1;
        }
    }

    // per-row sum of squares: quad shfl (lanes sharing a row) + cross-warp smem
#pragma unroll
    for (int mf = 0; mf < 2; mf++) {
        float s0 = 0.f, s1 = 0.f;
#pragma unroll
        for (int nf = 0; nf < 8; nf++) {
            s0 = fmaf(C[mf][nf][0], C[mf][nf][0], s0);
            s0 = fmaf(C[mf][nf][1], C[mf][nf][1], s0);
            s1 = fmaf(C[mf][nf][2], C[mf][nf][2], s1);
            s1 = fmaf(C[mf][nf][3], C[mf][nf][3], s1);
        }
        s0 += __shfl_xor_sync(0xffffffffu, s0, 1);
        s0 += __shfl_xor_sync(0xffffffffu, s0, 2);
        s1 += __shfl_xor_sync(0xffffffffu, s1, 1);
        s1 += __shfl_xor_sync(0xffffffffu, s1, 2);
        if (q == 0) {
            int r0 = wm * 32 + mf * 16 + g;
            red2[r0][wn] = s0;
            red2[r0 + 8][wn] = s1;
        }
    }
    __syncthreads();
    if (t < BM) {
        float ss = red2[t][0] + red2[t][1];
        int gn = n0 + t;
        if (which == 2) {
            float ns = sqrtf(ss);
            fac[t] = asinhf(ns) / fmaxf(ns, EPSF);
        } else {
            fac[t] = 1.f;
            if (gn < NN) {
                float* dst = (which == 0) ? g_q : g_k;
                dst[((size_t)gn * HH + h) * QKS + 128] = sqrtf(ss + 1.0f);
            }
        }
    }
    __syncthreads();

    // scaled stores (float2 per fragment half)
#pragma unroll
    for (int mf = 0; mf < 2; mf++) {
        int r0 = wm * 32 + mf * 16 + g;
#pragma unroll
        for (int half = 0; half < 2; half++) {
            int r = r0 + half * 8;
            int gn = n0 + r;
            if (gn >= NN) continue;
            float f = fac[r];
            float* base;
            if (which == 2) base = g_tan + ((size_t)gn * HH + h) * DD;
            else            base = ((which == 0) ? g_q : g_k) + ((size_t)gn * HH + h) * QKS;
#pragma unroll
            for (int nf = 0; nf < 8; nf++) {
                int col = wn * 64 + nf * 8 + q * 2;
                float2 v;
                v.x = C[mf][nf][half * 2] * f;
                v.y = C[mf][nf][half * 2 + 1] * f;
                *(float2*)(base + col) = v;
            }
        }
    }
}

// ---------------- edge phase (edges sorted by src) ---------------------------
__device__ __forceinline__ void atomicMaxF(float* addr, float v) {
    if (v >= 0.f) atomicMax((int*)addr, __float_as_int(v));
    else          atomicMin((unsigned int*)addr, __float_as_uint(v));
}

// warp per sorted edge: logits for 4 heads; k[src] L1/L2-cached via sort.
__global__ void k_edge1(const float* __restrict__ ef,
                        const float* __restrict__ We) {
    int p = (blockIdx.x * blockDim.x + threadIdx.x) >> 5;
    int lane = threadIdx.x & 31;
    if (p >= EE) return;
    int s = g_es[p];
    int d = g_ed[p];
    int e = g_eid[p];
    float efl = __ldg(ef + (size_t)e * EDD + lane);

    const float* qb = g_q + (size_t)d * (HH * QKS);
    const float* kb = g_k + (size_t)s * (HH * QKS);
    float part[HH];
#pragma unroll
    for (int h = 0; h < HH; h++) {
        const float* qh = qb + h * QKS;
        const float* kh = kb + h * QKS;
        float4 q4 = __ldg((const float4*)qh + lane);
        float4 k4 = __ldg((const float4*)kh + lane);
        float pp = q4.x * k4.x + q4.y * k4.y + q4.z * k4.z + q4.w * k4.w;
        if (lane == 0) pp = fmaf(-__ldg(qh + 128), __ldg(kh + 128), pp);
        pp = fmaf(CHALF * efl, __ldg(We + h * EDD + lane), pp);
        part[h] = pp;
    }
#pragma unroll
    for (int off = 16; off > 0; off >>= 1) {
#pragma unroll
        for (int h = 0; h < HH; h++)
            part[h] += __shfl_xor_sync(0xffffffffu, part[h], off);
    }
    if (lane < HH) {
        float logit = (2.f + 2.f * part[lane]) * SCALE_INV;
        g_logits[(size_t)p * HH + lane] = logit;
        atomicMaxF(&g_m[(size_t)d * HH + lane], logit);
    }
}

// thread per (sorted-edge, head): exp + denominator
__global__ void k_edge2() {
    int idx = blockIdx.x * blockDim.x + threadIdx.x;
    if (idx >= EE * HH) return;
    int p = idx >> 2, h = idx & 3;
    int d = g_ed[p];
    float ex = __expf(g_logits[idx] - g_m[(size_t)d * HH + h]);
    g_logits[idx] = ex;
    atomicAdd(&g_den[(size_t)d * HH + h], ex);
}

// warp per src-sorted edge: head-fused alpha*tan scatter via red.v4
__global__ void k_edge3() {
    int p = (blockIdx.x * blockDim.x + threadIdx.x) >> 5;
    int lane = threadIdx.x & 31;
    if (p >= EE) return;
    int s = g_es[p];
    int d = g_ed[p];
    float a_l = 0.f;
    if (lane < HH) a_l = g_logits[(size_t)p * HH + lane] /
                         g_den[(size_t)d * HH + lane];
    float alpha[HH];
#pragma unroll
    for (int h = 0; h < HH; h++) alpha[h] = __shfl_sync(0xffffffffu, a_l, h);

    const float4* tb = (const float4*)(g_tan + (size_t)s * (HH * DD));
    float4 t0 = __ldg(tb + lane);
    float4 t1 = __ldg(tb + 32 + lane);
    float4 t2 = __ldg(tb + 64 + lane);
    float4 t3 = __ldg(tb + 96 + lane);
    float cx = alpha[0] * t0.x + alpha[1] * t1.x + alpha[2] * t2.x + alpha[3] * t3.x;
    float cy = alpha[0] * t0.y + alpha[1] * t1.y + alpha[2] * t2.y + alpha[3] * t3.y;
    float cz = alpha[0] * t0.z + alpha[1] * t1.z + alpha[2] * t2.z + alpha[3] * t3.z;
    float cw = alpha[0] * t0.w + alpha[1] * t1.w + alpha[2] * t2.w + alpha[3] * t3.w;
    float* dp = g_agg + (size_t)d * DD + lane * 4;
    asm volatile("red.global.add.v4.f32 [%0], {%1, %2, %3, %4};"
                 :: "l"(dp), "f"(cx), "f"(cy), "f"(cz), "f"(cw) : "memory");
}

// ---------------- output: mean over heads + expmap0 -------------------------
__global__ void k_out(float* __restrict__ out) {
    int w = (blockIdx.x * blockDim.x + threadIdx.x) >> 5;
    int lane = threadIdx.x & 31;
    if (w >= NN) return;
    float4 v = ((const float4*)g_agg)[(size_t)w * 32 + lane];
    float4 ms = make_float4(v.x * 0.25f, v.y * 0.25f, v.z * 0.25f, v.w * 0.25f);
    float ss = ms.x * ms.x + ms.y * ms.y + ms.z * ms.z + ms.w * ms.w;
#pragma unroll
    for (int off = 16; off > 0; off >>= 1) ss += __shfl_xor_sync(0xffffffffu, ss, off);
    float nrm = sqrtf(ss);
    float f = sinhf(nrm) / fmaxf(nrm, EPSF);
    float* op = out + (size_t)w * KDIM;
    if (lane == 0) op[0] = coshf(nrm);
    float* sp = op + 1 + lane * 4;
    sp[0] = f * ms.x; sp[1] = f * ms.y; sp[2] = f * ms.z; sp[3] = f * ms.w;
}

// ---------------------------------------------------------------------------
extern "C" void kernel_launch(void* const* d_in, const int* in_sizes, int n_in,
                              void* d_out, int out_size) {
    const float* x  = (const float*)d_in[0];
    const int*   ei = (const int*)d_in[1];
    const float* ef = (const float*)d_in[2];
    const float* Wq = (const float*)d_in[3];
    const float* bq = (const float*)d_in[4];
    const float* Wk = (const float*)d_in[5];
    const float* bk = (const float*)d_in[6];
    const float* Wv = (const float*)d_in[7];
    const float* bv = (const float*)d_in[8];
    const float* We = (const float*)d_in[9];
    float* out = (float*)d_out;

    k_init<<<2048, 256>>>();
    k_hist<<<(EE + 255) / 256, 256>>>(ei);
    k_scanA<<<NBLK, 256>>>();
    k_gemm<<<dim3((NN + BM - 1) / BM, 12), 256>>>(x, Wq, bq, Wk, bk, Wv, bv);  // 4th launch (profiled)
    k_scanB<<<1, 256>>>();
    k_scanC<<<(NN + 255) / 256, 256>>>();
    k_scatter<<<(EE + 255) / 256, 256>>>(ei);
    k_edge1<<<(EE * 32) / 256, 256>>>(ef, We);
    k_edge2<<<(EE * HH + 255) / 256, 256>>>();
    k_edge3<<<(EE * 32) / 256, 256>>>();
    k_out<<<(NN * 32 + 255) / 256, 256>>>(out);
}

// round 11
// speedup vs baseline: 1.4386x; 1.0123x over previous
#include <cuda_runtime.h>
#include <math.h>

// Problem constants
#define NN   50000
#define EE   800000
#define DD   128
#define HH   4
#define EDD  32
#define KDIM 129          // D+1 input dim (time at index 0)
#define QKS  132          // per-(n,h) stride for q/k: [space 0..127, time at 128, pad]
#define EPSF 1e-8f
#define SCALE_INV 0.08838834764831845f   // 1/sqrt(128)
#define CHALF     5.656854249492381f     // sqrt(128)/2

#define NPAD 50176        // NN padded to 256 multiple (196 blocks)
#define NBLK 196

// ---------------- scratch (static device globals; no allocation) -------------
__device__ float g_q[NN * HH * QKS];      // 105.6 MB
__device__ float g_k[NN * HH * QKS];      // 105.6 MB
__device__ float g_tan[NN * HH * DD];     // 102.4 MB
__device__ float g_logits[EE * HH];       // 12.8 MB (logits, then exp values)
__device__ float g_m[NN * HH];
__device__ float g_den[NN * HH];
__device__ float g_agg[NN * DD];          // 25.6 MB (head-fused accumulator)
__device__ float g_wh[12 * DD * DD];      // tf32-hi of W (space dims), [wh][col][k]
__device__ float g_wl[12 * DD * DD];      // tf32-lo of W
__device__ int   g_cnt[NPAD];
__device__ int   g_scan[NPAD];
__device__ int   g_bsum[256];
__device__ int   g_off[NN + 1];
__device__ int   g_pos[NN];
__device__ int   g_es[EE];                // src, sorted by src
__device__ int   g_ed[EE];                // dst, sorted by src
__device__ int   g_eid[EE];               // original edge id, sorted by src

// ---------------------------------------------------------------------------
__global__ void k_init() {
    int i = blockIdx.x * blockDim.x + threadIdx.x;
    int stride = gridDim.x * blockDim.x;
    for (int j = i; j < NN * DD; j += stride) g_agg[j] = 0.f;
    for (int j = i; j < NN * HH; j += stride) { g_m[j] = -3.0e38f; g_den[j] = 0.f; }
    for (int j = i; j < NPAD; j += stride) g_cnt[j] = 0;
    for (int j = i; j < NN; j += stride) g_pos[j] = 0;
}

// ---------------- counting sort by SRC --------------------------------------
__global__ void k_hist(const int* __restrict__ ei) {
    int e = blockIdx.x * blockDim.x + threadIdx.x;
    if (e >= EE) return;
    atomicAdd(&g_cnt[ei[e]], 1);
}

__global__ void k_scanA() {
    __shared__ int sh[256];
    int b = blockIdx.x, t = threadIdx.x;
    int i = b * 256 + t;
    int v = g_cnt[i];
    sh[t] = v;
    __syncthreads();
#pragma unroll
    for (int o = 1; o < 256; o <<= 1) {
        int x = (t >= o) ? sh[t - o] : 0;
        __syncthreads();
        sh[t] += x;
        __syncthreads();
    }
    g_scan[i] = sh[t];
    if (t == 255) g_bsum[b] = sh[255];
}

__global__ void k_scanB() {
    __shared__ int sh[256];
    int t = threadIdx.x;
    int v = (t < NBLK) ? g_bsum[t] : 0;
    sh[t] = v;
    __syncthreads();
#pragma unroll
    for (int o = 1; o < 256; o <<= 1) {
        int x = (t >= o) ? sh[t - o] : 0;
        __syncthreads();
        sh[t] += x;
        __syncthreads();
    }
    g_bsum[t] = sh[t] - v;   // exclusive
    if (t == 0) g_off[NN] = EE;
}

__global__ void k_scanC() {
    int i = blockIdx.x * blockDim.x + threadIdx.x;
    if (i >= NN) return;
    g_off[i] = g_scan[i] - g_cnt[i] + g_bsum[i >> 8];  // exclusive prefix
}

__global__ void k_scatter(const int* __restrict__ ei) {
    int e = blockIdx.x * blockDim.x + threadIdx.x;
    if (e >= EE) return;
    int s = ei[e];
    int d = ei[EE + e];
    int p = g_off[s] + atomicAdd(&g_pos[s], 1);
    g_es[p] = s;
    g_ed[p] = d;
    g_eid[p] = e;
}

// ---------------- cp.async helpers ------------------------------------------
__device__ __forceinline__ void cpa4(void* dst, const void* src, int sz) {
    unsigned ds = (unsigned)__cvta_generic_to_shared(dst);
    asm volatile("cp.async.ca.shared.global [%0], [%1], 4, %2;"
                 :: "r"(ds), "l"(src), "r"(sz));
}
__device__ __forceinline__ void cpa16(void* dst, const void* src) {
    unsigned ds = (unsigned)__cvta_generic_to_shared(dst);
    asm volatile("cp.async.cg.shared.global [%0], [%1], 16;"
                 :: "r"(ds), "l"(src));
}
__device__ __forceinline__ void cpa_commit() {
    asm volatile("cp.async.commit_group;" ::: "memory");
}
__device__ __forceinline__ void cpa_wait0() {
    asm volatile("cp.async.wait_group 0;" ::: "memory");
}

// ---------------- tf32 split + mma helpers ----------------------------------
__device__ __forceinline__ void split_tf32(float v, unsigned& hi, unsigned& lo) {
    asm("cvt.rna.tf32.f32 %0, %1;" : "=r"(hi) : "f"(v));
    float l = v - __uint_as_float(hi);
    asm("cvt.rna.tf32.f32 %0, %1;" : "=r"(lo) : "f"(l));
}
__device__ __forceinline__ void mma8(float* c, const unsigned* a, unsigned b0, unsigned b1) {
    asm volatile("mma.sync.aligned.m16n8k8.row.col.f32.tf32.tf32.f32 "
                 "{%0,%1,%2,%3}, {%4,%5,%6,%7}, {%8,%9}, {%0,%1,%2,%3};"
                 : "+f"(c[0]), "+f"(c[1]), "+f"(c[2]), "+f"(c[3])
                 : "r"(a[0]), "r"(a[1]), "r"(a[2]), "r"(a[3]), "r"(b0), "r"(b1));
}

// ---------------- pre-split W (space dims i=1..128) into tf32 hi/lo ----------
__global__ void k_wsplit(const float* __restrict__ Wq,
                         const float* __restrict__ Wk,
                         const float* __restrict__ Wv) {
    int idx = blockIdx.x * blockDim.x + threadIdx.x;
    if (idx >= 12 * DD * DD) return;
    int wh = idx >> 14;            // /16384
    int rem = idx & 16383;
    int col = rem >> 7, k = rem & 127;
    int which = wh >> 2, h = wh & 3;
    const float* W = (which == 0) ? Wq : ((which == 1) ? Wk : Wv);
    float v = W[((h * DD) + col) * KDIM + 1 + k];
    unsigned hi, lo;
    split_tf32(v, hi, lo);
    g_wh[idx] = __uint_as_float(hi);
    g_wl[idx] = __uint_as_float(lo);
}

// ---------------- fused q/k/v GEMM via 3xTF32 tensor-core mma ----------------
// MMA over K=128 (x space dims i=1..128); x time (i=0) applied as rank-1 FMA
// in the epilogue. B-side splits precomputed globally (g_wh/g_wl).
// Block 128x128, 8 warps (4m x 2n). smem rows padded to 12 (conflict-free).
#define BM 128
#define BKK 8
#define NITK 16
__global__ void __launch_bounds__(256, 2)
k_gemm(const float* __restrict__ x,
       const float* __restrict__ Wq, const float* __restrict__ bq,
       const float* __restrict__ Wk, const float* __restrict__ bk,
       const float* __restrict__ Wv, const float* __restrict__ bv) {
    int which = blockIdx.y >> 2;
    int h = blockIdx.y & 3;
    const float* W = (which == 0) ? Wq : ((which == 1) ? Wk : Wv);
    const float* b = (which == 0) ? bq : ((which == 1) ? bk : bv);
    W += h * DD * KDIM;
    b += h * DD;
    const float* WhT = g_wh + (size_t)blockIdx.y * (DD * DD);
    const float* WlT = g_wl + (size_t)blockIdx.y * (DD * DD);
    int n0 = blockIdx.x * BM;

    __shared__ float    As[2][BM][12];
    __shared__ unsigned Bh[2][DD][12];
    __shared__ unsigned Bl[2][DD][12];
    __shared__ float red2[BM][2];
    __shared__ float fac[BM];
    __shared__ float xts[BM];

    int t = threadIdx.x;
    int wid = t >> 5, lane = t & 31;
    int wm = wid & 3, wn = wid >> 2;      // warp grid 4(m) x 2(n)
    int g = lane >> 2, q = lane & 3;

    float C[2][8][4];
#pragma unroll
    for (int mf = 0; mf < 2; mf++)
#pragma unroll
        for (int nf = 0; nf < 8; nf++)
#pragma unroll
            for (int c = 0; c < 4; c++) C[mf][nf][c] = 0.f;

    // x time column for epilogue rank-1
    if (t < BM) {
        int gn = n0 + t;
        xts[t] = (gn < NN) ? __ldg(x + (size_t)gn * KDIM) : 0.f;
    }

    auto issueTile = [&](int kk, int buf) {
        // A: 4x cp.async 4B per thread (x space dims, k-offset 1+kk)
#pragma unroll
        for (int r = 0; r < 4; r++) {
            int idx = r * 256 + t;
            int m = idx >> 3, k = idx & 7;
            int gn = n0 + m;
            bool ok = gn < NN;
            const float* src = ok ? (x + (size_t)gn * KDIM + 1 + kk + k) : x;
            cpa4(&As[buf][m][k], src, ok ? 4 : 0);
        }
        // B hi/lo: one 16B chunk each per thread (pre-split, fully valid)
        {
            int col = t >> 1, half = t & 1;
            cpa16(&Bh[buf][col][half * 4], WhT + col * DD + kk + half * 4);
            cpa16(&Bl[buf][col][half * 4], WlT + col * DD + kk + half * 4);
        }
        cpa_commit();
    };

    issueTile(0, 0);
    cpa_wait0();
    __syncthreads();

    for (int it = 0; it < NITK; it++) {
        int cur = it & 1;
        if (it + 1 < NITK) issueTile((it + 1) * BKK, cur ^ 1);
        unsigned ah[2][4], al[2][4];
#pragma unroll
        for (int mf = 0; mf < 2; mf++) {
            int m0 = wm * 32 + mf * 16 + g;
            split_tf32(As[cur][m0][q],     ah[mf][0], al[mf][0]);
            split_tf32(As[cur][m0 + 8][q], ah[mf][1], al[mf][1]);
            split_tf32(As[cur][m0][q + 4],     ah[mf][2], al[mf][2]);
            split_tf32(As[cur][m0 + 8][q + 4], ah[mf][3], al[mf][3]);
        }
#pragma unroll
        for (int nf = 0; nf < 8; nf++) {
            int nc = wn * 64 + nf * 8 + g;
            unsigned bh0 = Bh[cur][nc][q], bh1 = Bh[cur][nc][q + 4];
            unsigned bl0 = Bl[cur][nc][q], bl1 = Bl[cur][nc][q + 4];
#pragma unroll
            for (int mf = 0; mf < 2; mf++) {
                mma8(C[mf][nf], ah[mf], bh0, bh1);   // hi*hi
                mma8(C[mf][nf], ah[mf], bl0, bl1);   // hi*lo
                mma8(C[mf][nf], al[mf], bh0, bh1);   // lo*hi
            }
        }
        cpa_wait0();
        __syncthreads();
    }

    // rank-1 update for x time column (i=0): acc += xt[row] * W[col][0]
#pragma unroll
    for (int nf = 0; nf < 8; nf++) {
        int col = wn * 64 + nf * 8 + q * 2;
        float w0 = __ldg(W + col * KDIM);
        float w1 = __ldg(W + (col + 1) * KDIM);
#pragma unroll
        for (int mf = 0; mf < 2; mf++) {
            int r0 = wm * 32 + mf * 16 + g;
            float xt0 = xts[r0], xt1 = xts[r0 + 8];
            C[mf][nf][0] = fmaf(xt0, w0, C[mf][nf][0]);
            C[mf][nf][1] = fmaf(xt0, w1, C[mf][nf][1]);
            C[mf][nf][2] = fmaf(xt1, w0, C[mf][nf][2]);
            C[mf][nf][3] = fmaf(xt1, w1, C[mf][nf][3]);
        }
    }

    // bias (before row-norm, per reference)
#pragma unroll
    for (int nf = 0; nf < 8; nf++) {
        int col = wn * 64 + nf * 8 + q * 2;
        float b0 = __ldg(b + col);
        float b1 = __ldg(b + col + 1);
#pragma unroll
        for (int mf = 0; mf < 2; mf++) {
            C[mf][nf][0] += b0; C[mf][nf][1] += b1;
            C[mf][nf][2] += b0; C[mf][nf][3] += b1;
        }
    }

    // per-row sum of squares: quad shfl + cross-warp smem
#pragma unroll
    for (int mf = 0; mf < 2; mf++) {
        float s0 = 0.f, s1 = 0.f;
#pragma unroll
        for (int nf = 0; nf < 8; nf++) {
            s0 = fmaf(C[mf][nf][0], C[mf][nf][0], s0);
            s0 = fmaf(C[mf][nf][1], C[mf][nf][1], s0);
            s1 = fmaf(C[mf][nf][2], C[mf][nf][2], s1);
            s1 = fmaf(C[mf][nf][3], C[mf][nf][3], s1);
        }
        s0 += __shfl_xor_sync(0xffffffffu, s0, 1);
        s0 += __shfl_xor_sync(0xffffffffu, s0, 2);
        s1 += __shfl_xor_sync(0xffffffffu, s1, 1);
        s1 += __shfl_xor_sync(0xffffffffu, s1, 2);
        if (q == 0) {
            int r0 = wm * 32 + mf * 16 + g;
            red2[r0][wn] = s0;
            red2[r0 + 8][wn] = s1;
        }
    }
    __syncthreads();
    if (t < BM) {
        float ss = red2[t][0] + red2[t][1];
        int gn = n0 + t;
        if (which == 2) {
            float ns = sqrtf(ss);
            fac[t] = asinhf(ns) / fmaxf(ns, EPSF);
        } else {
            fac[t] = 1.f;
            if (gn < NN) {
                float* dst = (which == 0) ? g_q : g_k;
                dst[((size_t)gn * HH + h) * QKS + 128] = sqrtf(ss + 1.0f);
            }
        }
    }
    __syncthreads();

    // scaled stores (float2 per fragment half)
#pragma unroll
    for (int mf = 0; mf < 2; mf++) {
        int r0 = wm * 32 + mf * 16 + g;
#pragma unroll
        for (int half = 0; half < 2; half++) {
            int r = r0 + half * 8;
            int gn = n0 + r;
            if (gn >= NN) continue;
            float f = fac[r];
            float* base;
            if (which == 2) base = g_tan + ((size_t)gn * HH + h) * DD;
            else            base = ((which == 0) ? g_q : g_k) + ((size_t)gn * HH + h) * QKS;
#pragma unroll
            for (int nf = 0; nf < 8; nf++) {
                int col = wn * 64 + nf * 8 + q * 2;
                float2 v;
                v.x = C[mf][nf][half * 2] * f;
                v.y = C[mf][nf][half * 2 + 1] * f;
                *(float2*)(base + col) = v;
            }
        }
    }
}

// ---------------- edge phase (edges sorted by src) ---------------------------
__device__ __forceinline__ void atomicMaxF(float* addr, float v) {
    if (v >= 0.f) atomicMax((int*)addr, __float_as_int(v));
    else          atomicMin((unsigned int*)addr, __float_as_uint(v));
}

// warp per sorted edge: logits for 4 heads; k[src] L1/L2-cached via sort.
__global__ void k_edge1(const float* __restrict__ ef,
                        const float* __restrict__ We) {
    int p = (blockIdx.x * blockDim.x + threadIdx.x) >> 5;
    int lane = threadIdx.x & 31;
    if (p >= EE) return;
    int s = g_es[p];
    int d = g_ed[p];
    int e = g_eid[p];
    float efl = __ldg(ef + (size_t)e * EDD + lane);

    const float* qb = g_q + (size_t)d * (HH * QKS);
    const float* kb = g_k + (size_t)s * (HH * QKS);
    float part[HH];
#pragma unroll
    for (int h = 0; h < HH; h++) {
        const float* qh = qb + h * QKS;
        const float* kh = kb + h * QKS;
        float4 q4 = __ldg((const float4*)qh + lane);
        float4 k4 = __ldg((const float4*)kh + lane);
        float pp = q4.x * k4.x + q4.y * k4.y + q4.z * k4.z + q4.w * k4.w;
        if (lane == 0) pp = fmaf(-__ldg(qh + 128), __ldg(kh + 128), pp);
        pp = fmaf(CHALF * efl, __ldg(We + h * EDD + lane), pp);
        part[h] = pp;
    }
#pragma unroll
    for (int off = 16; off > 0; off >>= 1) {
#pragma unroll
        for (int h = 0; h < HH; h++)
            part[h] += __shfl_xor_sync(0xffffffffu, part[h], off);
    }
    if (lane < HH) {
        float logit = (2.f + 2.f * part[lane]) * SCALE_INV;
        g_logits[(size_t)p * HH + lane] = logit;
        atomicMaxF(&g_m[(size_t)d * HH + lane], logit);
    }
}

// thread per (sorted-edge, head): exp + denominator
__global__ void k_edge2() {
    int idx = blockIdx.x * blockDim.x + threadIdx.x;
    if (idx >= EE * HH) return;
    int p = idx >> 2, h = idx & 3;
    int d = g_ed[p];
    float ex = __expf(g_logits[idx] - g_m[(size_t)d * HH + h]);
    g_logits[idx] = ex;
    atomicAdd(&g_den[(size_t)d * HH + h], ex);
}

// warp per src-sorted edge: head-fused alpha*tan scatter via red.v4
__global__ void k_edge3() {
    int p = (blockIdx.x * blockDim.x + threadIdx.x) >> 5;
    int lane = threadIdx.x & 31;
    if (p >= EE) return;
    int s = g_es[p];
    int d = g_ed[p];
    float a_l = 0.f;
    if (lane < HH) a_l = g_logits[(size_t)p * HH + lane] /
                         g_den[(size_t)d * HH + lane];
    float alpha[HH];
#pragma unroll
    for (int h = 0; h < HH; h++) alpha[h] = __shfl_sync(0xffffffffu, a_l, h);

    const float4* tb = (const float4*)(g_tan + (size_t)s * (HH * DD));
    float4 t0 = __ldg(tb + lane);
    float4 t1 = __ldg(tb + 32 + lane);
    float4 t2 = __ldg(tb + 64 + lane);
    float4 t3 = __ldg(tb + 96 + lane);
    float cx = alpha[0] * t0.x + alpha[1] * t1.x + alpha[2] * t2.x + alpha[3] * t3.x;
    float cy = alpha[0] * t0.y + alpha[1] * t1.y + alpha[2] * t2.y + alpha[3] * t3.y;
    float cz = alpha[0] * t0.z + alpha[1] * t1.z + alpha[2] * t2.z + alpha[3] * t3.z;
    float cw = alpha[0] * t0.w + alpha[1] * t1.w + alpha[2] * t2.w + alpha[3] * t3.w;
    float* dp = g_agg + (size_t)d * DD + lane * 4;
    asm volatile("red.global.add.v4.f32 [%0], {%1, %2, %3, %4};"
                 :: "l"(dp), "f"(cx), "f"(cy), "f"(cz), "f"(cw) : "memory");
}

// ---------------- output: mean over heads + expmap0 -------------------------
__global__ void k_out(float* __restrict__ out) {
    int w = (blockIdx.x * blockDim.x + threadIdx.x) >> 5;
    int lane = threadIdx.x & 31;
    if (w >= NN) return;
    float4 v = ((const float4*)g_agg)[(size_t)w * 32 + lane];
    float4 ms = make_float4(v.x * 0.25f, v.y * 0.25f, v.z * 0.25f, v.w * 0.25f);
    float ss = ms.x * ms.x + ms.y * ms.y + ms.z * ms.z + ms.w * ms.w;
#pragma unroll
    for (int off = 16; off > 0; off >>= 1) ss += __shfl_xor_sync(0xffffffffu, ss, off);
    float nrm = sqrtf(ss);
    float f = sinhf(nrm) / fmaxf(nrm, EPSF);
    float* op = out + (size_t)w * KDIM;
    if (lane == 0) op[0] = coshf(nrm);
    float* sp = op + 1 + lane * 4;
    sp[0] = f * ms.x; sp[1] = f * ms.y; sp[2] = f * ms.z; sp[3] = f * ms.w;
}

// ---------------------------------------------------------------------------
extern "C" void kernel_launch(void* const* d_in, const int* in_sizes, int n_in,
                              void* d_out, int out_size) {
    const float* x  = (const float*)d_in[0];
    const int*   ei = (const int*)d_in[1];
    const float* ef = (const float*)d_in[2];
    const float* Wq = (const float*)d_in[3];
    const float* bq = (const float*)d_in[4];
    const float* Wk = (const float*)d_in[5];
    const float* bk = (const float*)d_in[6];
    const float* Wv = (const float*)d_in[7];
    const float* bv = (const float*)d_in[8];
    const float* We = (const float*)d_in[9];
    float* out = (float*)d_out;

    k_init<<<2048, 256>>>();
    k_hist<<<(EE + 255) / 256, 256>>>(ei);
    k_wsplit<<<(12 * DD * DD + 255) / 256, 256>>>(Wq, Wk, Wv);
    k_gemm<<<dim3((NN + BM - 1) / BM, 12), 256>>>(x, Wq, bq, Wk, bk, Wv, bv);  // 4th launch (profiled)
    k_scanA<<<NBLK, 256>>>();
    k_scanB<<<1, 256>>>();
    k_scanC<<<(NN + 255) / 256, 256>>>();
    k_scatter<<<(EE + 255) / 256, 256>>>(ei);
    k_edge1<<<(EE * 32) / 256, 256>>>(ef, We);
    k_edge2<<<(EE * HH + 255) / 256, 256>>>();
    k_edge3<<<(EE * 32) / 256, 256>>>();
    k_out<<<(NN * 32 + 255) / 256, 256>>>(out);
}